// round 7
// baseline (speedup 1.0000x reference)
#include <cuda_runtime.h>
#include <math.h>

// Sinkhorn distance, B=4, P=2048, D=64, eps=0.1, max_iter=100, thresh=0.1
// Output layout: [cost(4) | pi(4*2048*2048) | C(4*2048*2048)]
// Structure: kC builds C and C^T (scratch). Each iteration = two identical
// coalesced row-LSE kernels (kStep over C for u, over C^T for v).

#define BB 4
#define PP 2048
#define DD 64
#define NROWS (BB*PP)                 // 8192
#define NEL ((size_t)BB*PP*PP)        // 16777216
#define S_CONST 14.426950408889634f   // (1/eps) * log2(e), eps = 0.1
#define EPSLN2  0.069314718055994531f // eps * ln2

__device__ float g_ct[NEL];           // C transposed (64MB scratch)
__device__ float g_u[NROWS];
__device__ float g_v[NROWS];
__device__ float g_err[NROWS];
__device__ float g_xn[NROWS];
__device__ float g_yn[NROWS];
__device__ float g_part[NROWS];
__device__ int   g_done[104];

__device__ __forceinline__ float ex2(float x) {
    float r;
    asm("ex2.approx.ftz.f32 %0, %1;" : "=f"(r) : "f"(x));
    return r;
}

__global__ void kInit() {
    int t = blockIdx.x * 256 + threadIdx.x;
    if (t < NROWS) { g_u[t] = 0.0f; g_v[t] = 0.0f; }
    if (t == 0) g_done[0] = 0;
}

// Row norms. One warp per row.
__global__ void kNorm(const float* __restrict__ x, const float* __restrict__ y) {
    int lane = threadIdx.x & 31;
    int gw = blockIdx.x * 8 + (threadIdx.x >> 5);
    const float* src = (gw < NROWS) ? x : y;
    float* dst = (gw < NROWS) ? g_xn : g_yn;
    int row = gw & (NROWS - 1);
    float2 v = ((const float2*)src)[row * 32 + lane];
    float s = fmaf(v.x, v.x, v.y * v.y);
    #pragma unroll
    for (int off = 16; off > 0; off >>= 1)
        s += __shfl_xor_sync(0xffffffffu, s, off);
    if (lane == 0) dst[row] = s;
}

// C[b,i,j] = ||x_i||^2 + ||y_j||^2 - 2 x_i . y_j ; also writes C^T.
__global__ __launch_bounds__(256) void kC(const float* __restrict__ x,
                                          const float* __restrict__ y,
                                          float* __restrict__ Cout) {
    __shared__ float xs[64][68];
    __shared__ float ys[64][68];
    int b  = blockIdx.z;
    int i0 = blockIdx.y * 64;
    int j0 = blockIdx.x * 64;
    for (int idx = threadIdx.x; idx < 64 * 64; idx += 256) {
        int i = idx >> 6, d = idx & 63;
        xs[d][i] = x[((size_t)(b * PP + i0 + i)) * DD + d];
        ys[d][i] = y[((size_t)(b * PP + j0 + i)) * DD + d];
    }
    __syncthreads();
    int tx = threadIdx.x & 15, ty = threadIdx.x >> 4;
    float acc[4][4] = {};
    #pragma unroll 16
    for (int d = 0; d < 64; d++) {
        float4 xv = *(const float4*)&xs[d][ty * 4];
        float4 yv = *(const float4*)&ys[d][tx * 4];
        acc[0][0] = fmaf(xv.x, yv.x, acc[0][0]);
        acc[0][1] = fmaf(xv.x, yv.y, acc[0][1]);
        acc[0][2] = fmaf(xv.x, yv.z, acc[0][2]);
        acc[0][3] = fmaf(xv.x, yv.w, acc[0][3]);
        acc[1][0] = fmaf(xv.y, yv.x, acc[1][0]);
        acc[1][1] = fmaf(xv.y, yv.y, acc[1][1]);
        acc[1][2] = fmaf(xv.y, yv.z, acc[1][2]);
        acc[1][3] = fmaf(xv.y, yv.w, acc[1][3]);
        acc[2][0] = fmaf(xv.z, yv.x, acc[2][0]);
        acc[2][1] = fmaf(xv.z, yv.y, acc[2][1]);
        acc[2][2] = fmaf(xv.z, yv.z, acc[2][2]);
        acc[2][3] = fmaf(xv.z, yv.w, acc[2][3]);
        acc[3][0] = fmaf(xv.w, yv.x, acc[3][0]);
        acc[3][1] = fmaf(xv.w, yv.y, acc[3][1]);
        acc[3][2] = fmaf(xv.w, yv.z, acc[3][2]);
        acc[3][3] = fmaf(xv.w, yv.w, acc[3][3]);
    }
    int gi = b * PP + i0 + ty * 4;
    int gj = b * PP + j0 + tx * 4;
    float xn[4] = {g_xn[gi], g_xn[gi + 1], g_xn[gi + 2], g_xn[gi + 3]};
    float yn[4] = {g_yn[gj], g_yn[gj + 1], g_yn[gj + 2], g_yn[gj + 3]};
    float o[4][4];
    #pragma unroll
    for (int r = 0; r < 4; r++) {
        #pragma unroll
        for (int c = 0; c < 4; c++)
            o[r][c] = fmaf(-2.0f, acc[r][c], xn[r] + yn[c]);
    }
    #pragma unroll
    for (int r = 0; r < 4; r++) {
        float4 v = make_float4(o[r][0], o[r][1], o[r][2], o[r][3]);
        ((float4*)(Cout + ((size_t)(b * PP + i0 + ty * 4 + r)) * PP + j0))[tx] = v;
    }
    #pragma unroll
    for (int c = 0; c < 4; c++) {
        float4 v = make_float4(o[0][c], o[1][c], o[2][c], o[3][c]);
        *(float4*)(g_ct + ((size_t)(b * PP + j0 + tx * 4 + c)) * PP + i0 + ty * 4) = v;
    }
}

// One Sinkhorn half-step: out[r] = eps*log_mu - eps*LSE_k((win[k] - M[r,k])/eps).
// phase 0: M=C,  win=v, out=u (writes g_err).
// phase 1: M=CT, win=u, out=v (block 0 computes done flag from g_err).
// 2048 blocks x 256 threads; 4 rows/block, 2 warps/row, 32 elems/thread in regs.
__global__ __launch_bounds__(256) void kStep(const float* __restrict__ M,
                                             const float* __restrict__ win,
                                             float* __restrict__ wout,
                                             int iter, int phase,
                                             float eps_log_mu, float thresh_tot) {
    if (g_done[iter]) {
        if (phase == 1 && blockIdx.x == 0 && threadIdx.x == 0)
            g_done[iter + 1] = 1;
        return;
    }
    __shared__ __align__(16) float vs[PP];
    __shared__ float wm[8];
    __shared__ float ws[8];
    __shared__ float red[256];
    int tid = threadIdx.x;
    int b = blockIdx.x >> 9;                 // 512 blocks per batch
    const float4* vb = (const float4*)(win + b * PP);
    for (int t = tid; t < PP / 4; t += 256) {
        float4 v = vb[t];
        v.x *= S_CONST; v.y *= S_CONST; v.z *= S_CONST; v.w *= S_CONST;
        ((float4*)vs)[t] = v;
    }
    __syncthreads();
    int w    = tid >> 5;
    int lane = tid & 31;
    int r    = tid >> 6;                     // row-in-block 0..3
    int t64  = tid & 63;
    int row  = blockIdx.x * 4 + r;
    const float4* Mrow = (const float4*)(M + (size_t)row * PP);
    const float4* vs4  = (const float4*)vs;

    float4 av[8];
    float m0 = -INFINITY, m1 = -INFINITY, m2 = -INFINITY, m3 = -INFINITY;
    #pragma unroll
    for (int k = 0; k < 8; k++) {
        int idx = t64 + k * 64;
        float4 c4 = Mrow[idx];
        float4 v4 = vs4[idx];
        av[k].x = fmaf(c4.x, -S_CONST, v4.x);
        av[k].y = fmaf(c4.y, -S_CONST, v4.y);
        av[k].z = fmaf(c4.z, -S_CONST, v4.z);
        av[k].w = fmaf(c4.w, -S_CONST, v4.w);
        m0 = fmaxf(m0, av[k].x);
        m1 = fmaxf(m1, av[k].y);
        m2 = fmaxf(m2, av[k].z);
        m3 = fmaxf(m3, av[k].w);
    }
    float m = fmaxf(fmaxf(m0, m1), fmaxf(m2, m3));
    #pragma unroll
    for (int off = 16; off > 0; off >>= 1)
        m = fmaxf(m, __shfl_xor_sync(0xffffffffu, m, off));
    if (lane == 0) wm[w] = m;
    __syncthreads();
    m = fmaxf(wm[r * 2], wm[r * 2 + 1]);

    float s0 = 0.0f, s1 = 0.0f, s2 = 0.0f, s3 = 0.0f;
    #pragma unroll
    for (int k = 0; k < 8; k++) {
        s0 += ex2(av[k].x - m);
        s1 += ex2(av[k].y - m);
        s2 += ex2(av[k].z - m);
        s3 += ex2(av[k].w - m);
    }
    float s = (s0 + s1) + (s2 + s3);
    #pragma unroll
    for (int off = 16; off > 0; off >>= 1)
        s += __shfl_xor_sync(0xffffffffu, s, off);
    if (lane == 0) ws[w] = s;
    __syncthreads();
    if (t64 == 0) {
        float st = ws[r * 2] + ws[r * 2 + 1];
        float lse2 = m + __log2f(st);
        float un = fmaf(-EPSLN2, lse2, eps_log_mu);
        if (phase == 0) {
            float old = wout[row];
            wout[row] = un;
            g_err[row] = fabsf(un - old);
        } else {
            wout[row] = un;
        }
    }

    // phase 1, block 0: done flag from g_err (written by this iteration's U).
    if (phase == 1 && blockIdx.x == 0) {
        __syncthreads();
        float ts = 0.0f;
        #pragma unroll
        for (int k = 0; k < NROWS / 256; k++)
            ts += g_err[tid + k * 256];
        red[tid] = ts;
        __syncthreads();
        for (int st = 128; st > 0; st >>= 1) {
            if (tid < st) red[tid] += red[tid + st];
            __syncthreads();
        }
        if (tid == 0) g_done[iter + 1] = (red[0] < thresh_tot) ? 1 : 0;
    }
}

// pi = exp2((u+v-C)*S); per-row partial of sum(pi*C)
__global__ __launch_bounds__(256) void kFinal(const float* __restrict__ C,
                                              float* __restrict__ pi) {
    __shared__ __align__(16) float wsm[PP];
    __shared__ float red[256];
    int row = blockIdx.x;
    int b = row >> 11;
    float ui = g_u[row];
    const float4* vb = (const float4*)(g_v + b * PP);
    for (int t = threadIdx.x; t < PP / 4; t += 256) {
        float4 v4 = vb[t];
        v4.x = (ui + v4.x) * S_CONST;
        v4.y = (ui + v4.y) * S_CONST;
        v4.z = (ui + v4.z) * S_CONST;
        v4.w = (ui + v4.w) * S_CONST;
        ((float4*)wsm)[t] = v4;
    }
    __syncthreads();
    const float4* Crow = (const float4*)(C + (size_t)row * PP);
    float4* prow = (float4*)(pi + (size_t)row * PP);
    const float4* ws4 = (const float4*)wsm;
    float local = 0.0f;
    #pragma unroll
    for (int k = 0; k < 2; k++) {
        int idx = threadIdx.x + k * 256;
        float4 c4 = Crow[idx];
        float4 w4 = ws4[idx];
        float4 p4;
        p4.x = ex2(fmaf(c4.x, -S_CONST, w4.x));
        p4.y = ex2(fmaf(c4.y, -S_CONST, w4.y));
        p4.z = ex2(fmaf(c4.z, -S_CONST, w4.z));
        p4.w = ex2(fmaf(c4.w, -S_CONST, w4.w));
        prow[idx] = p4;
        local = fmaf(p4.x, c4.x, local);
        local = fmaf(p4.y, c4.y, local);
        local = fmaf(p4.z, c4.z, local);
        local = fmaf(p4.w, c4.w, local);
    }
    red[threadIdx.x] = local;
    __syncthreads();
    for (int st = 128; st > 0; st >>= 1) {
        if (threadIdx.x < st) red[threadIdx.x] += red[threadIdx.x + st];
        __syncthreads();
    }
    if (threadIdx.x == 0) g_part[row] = red[0];
}

__global__ void kCost(float* __restrict__ cost) {
    __shared__ float red[256];
    int b = blockIdx.x;
    float t = 0.0f;
    #pragma unroll
    for (int k = 0; k < 8; k++)
        t += g_part[b * 2048 + threadIdx.x + k * 256];
    red[threadIdx.x] = t;
    __syncthreads();
    for (int st = 128; st > 0; st >>= 1) {
        if (threadIdx.x < st) red[threadIdx.x] += red[threadIdx.x + st];
        __syncthreads();
    }
    if (threadIdx.x == 0) cost[b] = red[0];
}

extern "C" void kernel_launch(void* const* d_in, const int* in_sizes, int n_in,
                              void* d_out, int out_size) {
    const float* x = (const float*)d_in[0];
    const float* y = (const float*)d_in[1];
    float* out  = (float*)d_out;
    float* cost = out;                        // 4
    float* pi   = out + 4;                    // 16777216
    float* C    = out + 4 + (size_t)NEL;      // 16777216

    float* ct;
    cudaGetSymbolAddress((void**)&ct, g_ct);

    float log_mu = logf(1.0f / 2048.0f + 1e-8f);   // == log_nu (P1==P2)
    float eps_log_mu = 0.1f * log_mu;
    float thresh_tot = 0.1f * (float)BB;           // global-sum form of err<0.1

    float* u;  cudaGetSymbolAddress((void**)&u, g_u);
    float* v;  cudaGetSymbolAddress((void**)&v, g_v);

    kInit<<<(NROWS + 255) / 256, 256>>>();
    kNorm<<<2 * NROWS / 8, 256>>>(x, y);
    dim3 gC(PP / 64, PP / 64, BB);
    kC<<<gC, 256>>>(x, y, C);
    for (int it = 0; it < 100; it++) {
        kStep<<<NROWS / 4, 256>>>(C,  v, u, it, 0, eps_log_mu, thresh_tot);
        kStep<<<NROWS / 4, 256>>>(ct, u, v, it, 1, eps_log_mu, thresh_tot);
    }
    kFinal<<<NROWS, 256>>>(C, pi);
    kCost<<<BB, 256>>>(cost);
}

// round 8
// speedup vs baseline: 1.4211x; 1.4211x over previous
#include <cuda_runtime.h>
#include <math.h>

// Sinkhorn distance, B=4, P=2048, D=64, eps=0.1, max_iter=100, thresh=0.1
// Output layout: [cost(4) | pi(4*2048*2048) | C(4*2048*2048)]
// R3 structure (C is the ONLY iterated operand -> stays L2-resident):
//   kU: per-row LSE, one coalesced pass, exact two-sweep in registers.
//   kV: per-col LSE, ONE coalesced pass using exact online LSE (select form).

#define BB 4
#define PP 2048
#define DD 64
#define NROWS (BB*PP)                 // 8192
#define NEL ((size_t)BB*PP*PP)        // 16777216
#define S_CONST 14.426950408889634f   // (1/eps) * log2(e), eps = 0.1
#define EPSLN2  0.069314718055994531f // eps * ln2

__device__ float g_u[NROWS];
__device__ float g_v[NROWS];
__device__ float g_err[NROWS];
__device__ float g_xn[NROWS];
__device__ float g_yn[NROWS];
__device__ float g_part[NROWS];
__device__ int   g_done[104];

__device__ __forceinline__ float ex2(float x) {
    float r;
    asm("ex2.approx.ftz.f32 %0, %1;" : "=f"(r) : "f"(x));
    return r;
}

// Exact online LSE step (log2 domain): keeps true running max.
// 1 MUFU + ~5 fixed-lat ops, no branch (predicated select).
__device__ __forceinline__ void olse(float& m, float& s, float a) {
    float e = ex2(0.0f - fabsf(m - a));
    s = (a > m) ? fmaf(s, e, 1.0f) : (s + e);
    m = fmaxf(m, a);
}

// Merge two (max,sum) log2-domain accumulators.
__device__ __forceinline__ void lse_merge(float& m, float& s, float m2, float s2) {
    float M = fmaxf(m, m2);
    s = fmaf(s, ex2(m - M), s2 * ex2(m2 - M));
    m = M;
}

__global__ void kInit() {
    int t = blockIdx.x * 256 + threadIdx.x;
    if (t < NROWS) { g_u[t] = 0.0f; g_v[t] = 0.0f; }
    if (t == 0) g_done[0] = 0;
}

// Row norms. One warp per row.
__global__ void kNorm(const float* __restrict__ x, const float* __restrict__ y) {
    int lane = threadIdx.x & 31;
    int gw = blockIdx.x * 8 + (threadIdx.x >> 5);
    const float* src = (gw < NROWS) ? x : y;
    float* dst = (gw < NROWS) ? g_xn : g_yn;
    int row = gw & (NROWS - 1);
    float2 v = ((const float2*)src)[row * 32 + lane];
    float s = fmaf(v.x, v.x, v.y * v.y);
    #pragma unroll
    for (int off = 16; off > 0; off >>= 1)
        s += __shfl_xor_sync(0xffffffffu, s, off);
    if (lane == 0) dst[row] = s;
}

// C[b,i,j] = ||x_i||^2 + ||y_j||^2 - 2 x_i . y_j
__global__ __launch_bounds__(256) void kC(const float* __restrict__ x,
                                          const float* __restrict__ y,
                                          float* __restrict__ Cout) {
    __shared__ float xs[64][68];
    __shared__ float ys[64][68];
    int b  = blockIdx.z;
    int i0 = blockIdx.y * 64;
    int j0 = blockIdx.x * 64;
    for (int idx = threadIdx.x; idx < 64 * 64; idx += 256) {
        int i = idx >> 6, d = idx & 63;
        xs[d][i] = x[((size_t)(b * PP + i0 + i)) * DD + d];
        ys[d][i] = y[((size_t)(b * PP + j0 + i)) * DD + d];
    }
    __syncthreads();
    int tx = threadIdx.x & 15, ty = threadIdx.x >> 4;
    float acc[4][4] = {};
    #pragma unroll 16
    for (int d = 0; d < 64; d++) {
        float4 xv = *(const float4*)&xs[d][ty * 4];
        float4 yv = *(const float4*)&ys[d][tx * 4];
        acc[0][0] = fmaf(xv.x, yv.x, acc[0][0]);
        acc[0][1] = fmaf(xv.x, yv.y, acc[0][1]);
        acc[0][2] = fmaf(xv.x, yv.z, acc[0][2]);
        acc[0][3] = fmaf(xv.x, yv.w, acc[0][3]);
        acc[1][0] = fmaf(xv.y, yv.x, acc[1][0]);
        acc[1][1] = fmaf(xv.y, yv.y, acc[1][1]);
        acc[1][2] = fmaf(xv.y, yv.z, acc[1][2]);
        acc[1][3] = fmaf(xv.y, yv.w, acc[1][3]);
        acc[2][0] = fmaf(xv.z, yv.x, acc[2][0]);
        acc[2][1] = fmaf(xv.z, yv.y, acc[2][1]);
        acc[2][2] = fmaf(xv.z, yv.z, acc[2][2]);
        acc[2][3] = fmaf(xv.z, yv.w, acc[2][3]);
        acc[3][0] = fmaf(xv.w, yv.x, acc[3][0]);
        acc[3][1] = fmaf(xv.w, yv.y, acc[3][1]);
        acc[3][2] = fmaf(xv.w, yv.z, acc[3][2]);
        acc[3][3] = fmaf(xv.w, yv.w, acc[3][3]);
    }
    int gi = b * PP + i0 + ty * 4;
    int gj = b * PP + j0 + tx * 4;
    float xn[4] = {g_xn[gi], g_xn[gi + 1], g_xn[gi + 2], g_xn[gi + 3]};
    float yn[4] = {g_yn[gj], g_yn[gj + 1], g_yn[gj + 2], g_yn[gj + 3]};
    #pragma unroll
    for (int r = 0; r < 4; r++) {
        float4 o;
        o.x = fmaf(-2.0f, acc[r][0], xn[r] + yn[0]);
        o.y = fmaf(-2.0f, acc[r][1], xn[r] + yn[1]);
        o.z = fmaf(-2.0f, acc[r][2], xn[r] + yn[2]);
        o.w = fmaf(-2.0f, acc[r][3], xn[r] + yn[3]);
        ((float4*)(Cout + ((size_t)(b * PP + i0 + ty * 4 + r)) * PP + j0))[tx] = o;
    }
}

// u update: per-row LSE_j((v_j - C_ij)/eps). 4 rows/block, 64 threads/row,
// 32 elems/thread register-cached; exact two-sweep (1 ex2/elem).
__global__ __launch_bounds__(256) void kU(const float* __restrict__ C, int iter,
                                          float eps_log_mu) {
    if (g_done[iter]) return;
    __shared__ __align__(16) float vs[PP];
    __shared__ float wm[8];
    __shared__ float ws[8];
    int tid = threadIdx.x;
    int b = blockIdx.x >> 9;                 // 512 blocks per batch
    const float4* vb = (const float4*)(g_v + b * PP);
    for (int t = tid; t < PP / 4; t += 256) {
        float4 v = vb[t];
        v.x *= S_CONST; v.y *= S_CONST; v.z *= S_CONST; v.w *= S_CONST;
        ((float4*)vs)[t] = v;
    }
    __syncthreads();
    int w    = tid >> 5;
    int lane = tid & 31;
    int r    = tid >> 6;                     // row-in-block 0..3
    int t64  = tid & 63;
    int row  = blockIdx.x * 4 + r;
    const float4* Crow = (const float4*)(C + (size_t)row * PP);
    const float4* vs4  = (const float4*)vs;

    float4 av[8];
    float m0 = -INFINITY, m1 = -INFINITY, m2 = -INFINITY, m3 = -INFINITY;
    #pragma unroll
    for (int k = 0; k < 8; k++) {
        int idx = t64 + k * 64;
        float4 c4 = Crow[idx];
        float4 v4 = vs4[idx];
        av[k].x = fmaf(c4.x, -S_CONST, v4.x);
        av[k].y = fmaf(c4.y, -S_CONST, v4.y);
        av[k].z = fmaf(c4.z, -S_CONST, v4.z);
        av[k].w = fmaf(c4.w, -S_CONST, v4.w);
        m0 = fmaxf(m0, av[k].x);
        m1 = fmaxf(m1, av[k].y);
        m2 = fmaxf(m2, av[k].z);
        m3 = fmaxf(m3, av[k].w);
    }
    float m = fmaxf(fmaxf(m0, m1), fmaxf(m2, m3));
    #pragma unroll
    for (int off = 16; off > 0; off >>= 1)
        m = fmaxf(m, __shfl_xor_sync(0xffffffffu, m, off));
    if (lane == 0) wm[w] = m;
    __syncthreads();
    m = fmaxf(wm[r * 2], wm[r * 2 + 1]);

    float s0 = 0.0f, s1 = 0.0f, s2 = 0.0f, s3 = 0.0f;
    #pragma unroll
    for (int k = 0; k < 8; k++) {
        s0 += ex2(av[k].x - m);
        s1 += ex2(av[k].y - m);
        s2 += ex2(av[k].z - m);
        s3 += ex2(av[k].w - m);
    }
    float s = (s0 + s1) + (s2 + s3);
    #pragma unroll
    for (int off = 16; off > 0; off >>= 1)
        s += __shfl_xor_sync(0xffffffffu, s, off);
    if (lane == 0) ws[w] = s;
    __syncthreads();
    if (t64 == 0) {
        float st = ws[r * 2] + ws[r * 2 + 1];
        float lse2 = m + __log2f(st);
        float un = fmaf(-EPSLN2, lse2, eps_log_mu);
        float old = g_u[row];
        g_u[row] = un;
        g_err[row] = fabsf(un - old);
    }
}

// v update: per-col LSE_i((u_i - C_ij)/eps), SINGLE pass via exact online LSE.
// 128 blocks x 1024 threads. Block = 64-col stripe x all 2048 rows of a batch.
// Warp w: column half (w&1)*32 + lane, row group (w>>1)*128, two independent
// 64-row chains per thread. smem merge of 16 row-group partials per column.
// Block 0 additionally computes the done flag.
__global__ __launch_bounds__(1024) void kV(const float* __restrict__ C, int iter,
                                           float eps_log_nu, float thresh_tot) {
    __shared__ __align__(16) float us[PP];
    __shared__ float pm[16][64];
    __shared__ float ps[16][64];
    __shared__ float red[1024];
    int done = g_done[iter];
    int tid = threadIdx.x;
    int b  = blockIdx.x >> 5;
    int j0 = (blockIdx.x & 31) * 64;
    int w = tid >> 5, lane = tid & 31;

    if (!done) {
        const float4* ub = (const float4*)(g_u + b * PP);
        for (int t = tid; t < PP / 4; t += 1024) {
            float4 u4 = ub[t];
            u4.x *= S_CONST; u4.y *= S_CONST; u4.z *= S_CONST; u4.w *= S_CONST;
            ((float4*)us)[t] = u4;
        }
        __syncthreads();
        int h  = w & 1;                       // column half
        int g  = w >> 1;                      // row group 0..15
        int jc = h * 32 + lane;               // column within stripe 0..63
        int j  = j0 + jc;
        int r0 = g * 128;
        const float* pA = C + (size_t)b * PP * PP + (size_t)r0 * PP + j;
        const float* pB = pA + (size_t)64 * PP;
        const float* uA = us + r0;
        float mA = -INFINITY, sA = 0.0f, mB = -INFINITY, sB = 0.0f;
        #pragma unroll 8
        for (int rr = 0; rr < 64; rr++) {
            float cA = *pA; pA += PP;
            float cB = *pB; pB += PP;
            olse(mA, sA, fmaf(cA, -S_CONST, uA[rr]));
            olse(mB, sB, fmaf(cB, -S_CONST, uA[rr + 64]));
        }
        lse_merge(mA, sA, mB, sB);
        pm[g][jc] = mA;
        ps[g][jc] = sA;
        __syncthreads();
        if (tid < 64) {
            float M = pm[0][tid], S = ps[0][tid];
            #pragma unroll
            for (int k = 1; k < 16; k++)
                lse_merge(M, S, pm[k][tid], ps[k][tid]);
            float lse2 = M + __log2f(S);
            g_v[b * PP + j0 + tid] = fmaf(-EPSLN2, lse2, eps_log_nu);
        }
    }

    // done flag (block 0, deterministic fixed-order reduction of g_err)
    if (blockIdx.x == 0) {
        if (done) {
            if (tid == 0) g_done[iter + 1] = 1;
            return;
        }
        __syncthreads();
        float ts = 0.0f;
        #pragma unroll
        for (int k = 0; k < NROWS / 1024; k++)
            ts += g_err[tid + k * 1024];
        red[tid] = ts;
        __syncthreads();
        for (int st = 512; st > 0; st >>= 1) {
            if (tid < st) red[tid] += red[tid + st];
            __syncthreads();
        }
        if (tid == 0) g_done[iter + 1] = (red[0] < thresh_tot) ? 1 : 0;
    }
}

// pi = exp2((u+v-C)*S); per-row partial of sum(pi*C)
__global__ __launch_bounds__(256) void kFinal(const float* __restrict__ C,
                                              float* __restrict__ pi) {
    __shared__ __align__(16) float wsm[PP];
    __shared__ float red[256];
    int row = blockIdx.x;
    int b = row >> 11;
    float ui = g_u[row];
    const float4* vb = (const float4*)(g_v + b * PP);
    for (int t = threadIdx.x; t < PP / 4; t += 256) {
        float4 v4 = vb[t];
        v4.x = (ui + v4.x) * S_CONST;
        v4.y = (ui + v4.y) * S_CONST;
        v4.z = (ui + v4.z) * S_CONST;
        v4.w = (ui + v4.w) * S_CONST;
        ((float4*)wsm)[t] = v4;
    }
    __syncthreads();
    const float4* Crow = (const float4*)(C + (size_t)row * PP);
    float4* prow = (float4*)(pi + (size_t)row * PP);
    const float4* ws4 = (const float4*)wsm;
    float local = 0.0f;
    #pragma unroll
    for (int k = 0; k < 2; k++) {
        int idx = threadIdx.x + k * 256;
        float4 c4 = Crow[idx];
        float4 w4 = ws4[idx];
        float4 p4;
        p4.x = ex2(fmaf(c4.x, -S_CONST, w4.x));
        p4.y = ex2(fmaf(c4.y, -S_CONST, w4.y));
        p4.z = ex2(fmaf(c4.z, -S_CONST, w4.z));
        p4.w = ex2(fmaf(c4.w, -S_CONST, w4.w));
        prow[idx] = p4;
        local = fmaf(p4.x, c4.x, local);
        local = fmaf(p4.y, c4.y, local);
        local = fmaf(p4.z, c4.z, local);
        local = fmaf(p4.w, c4.w, local);
    }
    red[threadIdx.x] = local;
    __syncthreads();
    for (int st = 128; st > 0; st >>= 1) {
        if (threadIdx.x < st) red[threadIdx.x] += red[threadIdx.x + st];
        __syncthreads();
    }
    if (threadIdx.x == 0) g_part[row] = red[0];
}

__global__ void kCost(float* __restrict__ cost) {
    __shared__ float red[256];
    int b = blockIdx.x;
    float t = 0.0f;
    #pragma unroll
    for (int k = 0; k < 8; k++)
        t += g_part[b * 2048 + threadIdx.x + k * 256];
    red[threadIdx.x] = t;
    __syncthreads();
    for (int st = 128; st > 0; st >>= 1) {
        if (threadIdx.x < st) red[threadIdx.x] += red[threadIdx.x + st];
        __syncthreads();
    }
    if (threadIdx.x == 0) cost[b] = red[0];
}

extern "C" void kernel_launch(void* const* d_in, const int* in_sizes, int n_in,
                              void* d_out, int out_size) {
    const float* x = (const float*)d_in[0];
    const float* y = (const float*)d_in[1];
    float* out  = (float*)d_out;
    float* cost = out;                        // 4
    float* pi   = out + 4;                    // 16777216
    float* C    = out + 4 + (size_t)NEL;      // 16777216

    float log_mu = logf(1.0f / 2048.0f + 1e-8f);   // == log_nu (P1==P2)
    float eps_log_mu = 0.1f * log_mu;
    float thresh_tot = 0.1f * (float)BB;           // global-sum form of err<0.1

    kInit<<<(NROWS + 255) / 256, 256>>>();
    kNorm<<<2 * NROWS / 8, 256>>>(x, y);
    dim3 gC(PP / 64, PP / 64, BB);
    kC<<<gC, 256>>>(x, y, C);
    for (int it = 0; it < 100; it++) {
        kU<<<NROWS / 4, 256>>>(C, it, eps_log_mu);
        kV<<<BB * (PP / 64), 1024>>>(C, it, eps_log_mu, thresh_tot);
    }
    kFinal<<<NROWS, 256>>>(C, pi);
    kCost<<<BB, 256>>>(cost);
}

// round 9
// speedup vs baseline: 1.4811x; 1.0422x over previous
#include <cuda_runtime.h>
#include <math.h>

// Sinkhorn distance, B=4, P=2048, D=64, eps=0.1, max_iter=100, thresh=0.1
// Output layout: [cost(4) | pi(4*2048*2048) | C(4*2048*2048)]
// R8 structure + PDL (programmatic dependent launch) to hide the ~4us/node
// launch gap across the 200 serial iteration kernels.

#define BB 4
#define PP 2048
#define DD 64
#define NROWS (BB*PP)                 // 8192
#define NEL ((size_t)BB*PP*PP)        // 16777216
#define S_CONST 14.426950408889634f   // (1/eps) * log2(e), eps = 0.1
#define EPSLN2  0.069314718055994531f // eps * ln2

__device__ float g_u[NROWS];
__device__ float g_v[NROWS];
__device__ float g_err[NROWS];
__device__ float g_xn[NROWS];
__device__ float g_yn[NROWS];
__device__ float g_part[NROWS];
__device__ int   g_done[104];

#define PDL_WAIT() asm volatile("griddepcontrol.wait;" ::: "memory")

__device__ __forceinline__ float ex2(float x) {
    float r;
    asm("ex2.approx.ftz.f32 %0, %1;" : "=f"(r) : "f"(x));
    return r;
}

// Exact online LSE step (log2 domain): keeps true running max.
__device__ __forceinline__ void olse(float& m, float& s, float a) {
    float e = ex2(0.0f - fabsf(m - a));
    s = (a > m) ? fmaf(s, e, 1.0f) : (s + e);
    m = fmaxf(m, a);
}

// Merge two (max,sum) log2-domain accumulators.
__device__ __forceinline__ void lse_merge(float& m, float& s, float m2, float s2) {
    float M = fmaxf(m, m2);
    s = fmaf(s, ex2(m - M), s2 * ex2(m2 - M));
    m = M;
}

__global__ void kInit() {
    int t = blockIdx.x * 256 + threadIdx.x;
    if (t < NROWS) { g_u[t] = 0.0f; g_v[t] = 0.0f; }
    if (t == 0) g_done[0] = 0;
}

// Row norms. One warp per row.
__global__ void kNorm(const float* __restrict__ x, const float* __restrict__ y) {
    PDL_WAIT();
    int lane = threadIdx.x & 31;
    int gw = blockIdx.x * 8 + (threadIdx.x >> 5);
    const float* src = (gw < NROWS) ? x : y;
    float* dst = (gw < NROWS) ? g_xn : g_yn;
    int row = gw & (NROWS - 1);
    float2 v = ((const float2*)src)[row * 32 + lane];
    float s = fmaf(v.x, v.x, v.y * v.y);
    #pragma unroll
    for (int off = 16; off > 0; off >>= 1)
        s += __shfl_xor_sync(0xffffffffu, s, off);
    if (lane == 0) dst[row] = s;
}

// C[b,i,j] = ||x_i||^2 + ||y_j||^2 - 2 x_i . y_j
__global__ __launch_bounds__(256) void kC(const float* __restrict__ x,
                                          const float* __restrict__ y,
                                          float* __restrict__ Cout) {
    PDL_WAIT();
    __shared__ float xs[64][68];
    __shared__ float ys[64][68];
    int b  = blockIdx.z;
    int i0 = blockIdx.y * 64;
    int j0 = blockIdx.x * 64;
    for (int idx = threadIdx.x; idx < 64 * 64; idx += 256) {
        int i = idx >> 6, d = idx & 63;
        xs[d][i] = x[((size_t)(b * PP + i0 + i)) * DD + d];
        ys[d][i] = y[((size_t)(b * PP + j0 + i)) * DD + d];
    }
    __syncthreads();
    int tx = threadIdx.x & 15, ty = threadIdx.x >> 4;
    float acc[4][4] = {};
    #pragma unroll 16
    for (int d = 0; d < 64; d++) {
        float4 xv = *(const float4*)&xs[d][ty * 4];
        float4 yv = *(const float4*)&ys[d][tx * 4];
        acc[0][0] = fmaf(xv.x, yv.x, acc[0][0]);
        acc[0][1] = fmaf(xv.x, yv.y, acc[0][1]);
        acc[0][2] = fmaf(xv.x, yv.z, acc[0][2]);
        acc[0][3] = fmaf(xv.x, yv.w, acc[0][3]);
        acc[1][0] = fmaf(xv.y, yv.x, acc[1][0]);
        acc[1][1] = fmaf(xv.y, yv.y, acc[1][1]);
        acc[1][2] = fmaf(xv.y, yv.z, acc[1][2]);
        acc[1][3] = fmaf(xv.y, yv.w, acc[1][3]);
        acc[2][0] = fmaf(xv.z, yv.x, acc[2][0]);
        acc[2][1] = fmaf(xv.z, yv.y, acc[2][1]);
        acc[2][2] = fmaf(xv.z, yv.z, acc[2][2]);
        acc[2][3] = fmaf(xv.z, yv.w, acc[2][3]);
        acc[3][0] = fmaf(xv.w, yv.x, acc[3][0]);
        acc[3][1] = fmaf(xv.w, yv.y, acc[3][1]);
        acc[3][2] = fmaf(xv.w, yv.z, acc[3][2]);
        acc[3][3] = fmaf(xv.w, yv.w, acc[3][3]);
    }
    int gi = b * PP + i0 + ty * 4;
    int gj = b * PP + j0 + tx * 4;
    float xn[4] = {g_xn[gi], g_xn[gi + 1], g_xn[gi + 2], g_xn[gi + 3]};
    float yn[4] = {g_yn[gj], g_yn[gj + 1], g_yn[gj + 2], g_yn[gj + 3]};
    #pragma unroll
    for (int r = 0; r < 4; r++) {
        float4 o;
        o.x = fmaf(-2.0f, acc[r][0], xn[r] + yn[0]);
        o.y = fmaf(-2.0f, acc[r][1], xn[r] + yn[1]);
        o.z = fmaf(-2.0f, acc[r][2], xn[r] + yn[2]);
        o.w = fmaf(-2.0f, acc[r][3], xn[r] + yn[3]);
        ((float4*)(Cout + ((size_t)(b * PP + i0 + ty * 4 + r)) * PP + j0))[tx] = o;
    }
}

// u update: per-row LSE_j((v_j - C_ij)/eps). 8 rows/block, 64 threads/row,
// 32 elems/thread register-cached; exact two-sweep (1 ex2/elem).
__global__ __launch_bounds__(512) void kU(const float* __restrict__ C, int iter,
                                          float eps_log_mu) {
    PDL_WAIT();
    if (g_done[iter]) return;
    __shared__ __align__(16) float vs[PP];
    __shared__ float wm[16];
    __shared__ float ws[16];
    int tid = threadIdx.x;
    int b = blockIdx.x >> 8;                 // 256 blocks per batch
    const float4* vb = (const float4*)(g_v + b * PP);
    for (int t = tid; t < PP / 4; t += 512) {
        float4 v = vb[t];
        v.x *= S_CONST; v.y *= S_CONST; v.z *= S_CONST; v.w *= S_CONST;
        ((float4*)vs)[t] = v;
    }
    __syncthreads();
    int w    = tid >> 5;
    int lane = tid & 31;
    int r    = tid >> 6;                     // row-in-block 0..7
    int t64  = tid & 63;
    int row  = blockIdx.x * 8 + r;
    const float4* Crow = (const float4*)(C + (size_t)row * PP);
    const float4* vs4  = (const float4*)vs;

    float4 av[8];
    float m0 = -INFINITY, m1 = -INFINITY, m2 = -INFINITY, m3 = -INFINITY;
    #pragma unroll
    for (int k = 0; k < 8; k++) {
        int idx = t64 + k * 64;
        float4 c4 = Crow[idx];
        float4 v4 = vs4[idx];
        av[k].x = fmaf(c4.x, -S_CONST, v4.x);
        av[k].y = fmaf(c4.y, -S_CONST, v4.y);
        av[k].z = fmaf(c4.z, -S_CONST, v4.z);
        av[k].w = fmaf(c4.w, -S_CONST, v4.w);
        m0 = fmaxf(m0, av[k].x);
        m1 = fmaxf(m1, av[k].y);
        m2 = fmaxf(m2, av[k].z);
        m3 = fmaxf(m3, av[k].w);
    }
    float m = fmaxf(fmaxf(m0, m1), fmaxf(m2, m3));
    #pragma unroll
    for (int off = 16; off > 0; off >>= 1)
        m = fmaxf(m, __shfl_xor_sync(0xffffffffu, m, off));
    if (lane == 0) wm[w] = m;
    __syncthreads();
    m = fmaxf(wm[r * 2], wm[r * 2 + 1]);

    float s0 = 0.0f, s1 = 0.0f, s2 = 0.0f, s3 = 0.0f;
    #pragma unroll
    for (int k = 0; k < 8; k++) {
        s0 += ex2(av[k].x - m);
        s1 += ex2(av[k].y - m);
        s2 += ex2(av[k].z - m);
        s3 += ex2(av[k].w - m);
    }
    float s = (s0 + s1) + (s2 + s3);
    #pragma unroll
    for (int off = 16; off > 0; off >>= 1)
        s += __shfl_xor_sync(0xffffffffu, s, off);
    if (lane == 0) ws[w] = s;
    __syncthreads();
    if (t64 == 0) {
        float st = ws[r * 2] + ws[r * 2 + 1];
        float lse2 = m + __log2f(st);
        float un = fmaf(-EPSLN2, lse2, eps_log_mu);
        float old = g_u[row];
        g_u[row] = un;
        g_err[row] = fabsf(un - old);
    }
}

// v update: per-col LSE, SINGLE pass via exact online LSE.
// 128 blocks x 1024 threads; block = 64-col stripe x 2048 rows of one batch.
__global__ __launch_bounds__(1024) void kV(const float* __restrict__ C, int iter,
                                           float eps_log_nu, float thresh_tot) {
    PDL_WAIT();
    __shared__ __align__(16) float us[PP];
    __shared__ float pm[16][64];
    __shared__ float ps[16][64];
    __shared__ float red[1024];
    int done = g_done[iter];
    int tid = threadIdx.x;
    int b  = blockIdx.x >> 5;
    int j0 = (blockIdx.x & 31) * 64;
    int w = tid >> 5, lane = tid & 31;

    if (!done) {
        const float4* ub = (const float4*)(g_u + b * PP);
        for (int t = tid; t < PP / 4; t += 1024) {
            float4 u4 = ub[t];
            u4.x *= S_CONST; u4.y *= S_CONST; u4.z *= S_CONST; u4.w *= S_CONST;
            ((float4*)us)[t] = u4;
        }
        __syncthreads();
        int h  = w & 1;
        int g  = w >> 1;
        int jc = h * 32 + lane;
        int j  = j0 + jc;
        int r0 = g * 128;
        const float* pA = C + (size_t)b * PP * PP + (size_t)r0 * PP + j;
        const float* pB = pA + (size_t)64 * PP;
        const float* uA = us + r0;
        float mA = -INFINITY, sA = 0.0f, mB = -INFINITY, sB = 0.0f;
        #pragma unroll 8
        for (int rr = 0; rr < 64; rr++) {
            float cA = *pA; pA += PP;
            float cB = *pB; pB += PP;
            olse(mA, sA, fmaf(cA, -S_CONST, uA[rr]));
            olse(mB, sB, fmaf(cB, -S_CONST, uA[rr + 64]));
        }
        lse_merge(mA, sA, mB, sB);
        pm[g][jc] = mA;
        ps[g][jc] = sA;
        __syncthreads();
        if (tid < 64) {
            float M = pm[0][tid], S = ps[0][tid];
            #pragma unroll
            for (int k = 1; k < 16; k++)
                lse_merge(M, S, pm[k][tid], ps[k][tid]);
            float lse2 = M + __log2f(S);
            g_v[b * PP + j0 + tid] = fmaf(-EPSLN2, lse2, eps_log_nu);
        }
    }

    if (blockIdx.x == 0) {
        if (done) {
            if (tid == 0) g_done[iter + 1] = 1;
            return;
        }
        __syncthreads();
        float ts = 0.0f;
        #pragma unroll
        for (int k = 0; k < NROWS / 1024; k++)
            ts += g_err[tid + k * 1024];
        red[tid] = ts;
        __syncthreads();
        for (int st = 512; st > 0; st >>= 1) {
            if (tid < st) red[tid] += red[tid + st];
            __syncthreads();
        }
        if (tid == 0) g_done[iter + 1] = (red[0] < thresh_tot) ? 1 : 0;
    }
}

// pi = exp2((u+v-C)*S); per-row partial of sum(pi*C)
__global__ __launch_bounds__(256) void kFinal(const float* __restrict__ C,
                                              float* __restrict__ pi) {
    PDL_WAIT();
    __shared__ __align__(16) float wsm[PP];
    __shared__ float red[256];
    int row = blockIdx.x;
    int b = row >> 11;
    float ui = g_u[row];
    const float4* vb = (const float4*)(g_v + b * PP);
    for (int t = threadIdx.x; t < PP / 4; t += 256) {
        float4 v4 = vb[t];
        v4.x = (ui + v4.x) * S_CONST;
        v4.y = (ui + v4.y) * S_CONST;
        v4.z = (ui + v4.z) * S_CONST;
        v4.w = (ui + v4.w) * S_CONST;
        ((float4*)wsm)[t] = v4;
    }
    __syncthreads();
    const float4* Crow = (const float4*)(C + (size_t)row * PP);
    float4* prow = (float4*)(pi + (size_t)row * PP);
    const float4* ws4 = (const float4*)wsm;
    float local = 0.0f;
    #pragma unroll
    for (int k = 0; k < 2; k++) {
        int idx = threadIdx.x + k * 256;
        float4 c4 = Crow[idx];
        float4 w4 = ws4[idx];
        float4 p4;
        p4.x = ex2(fmaf(c4.x, -S_CONST, w4.x));
        p4.y = ex2(fmaf(c4.y, -S_CONST, w4.y));
        p4.z = ex2(fmaf(c4.z, -S_CONST, w4.z));
        p4.w = ex2(fmaf(c4.w, -S_CONST, w4.w));
        prow[idx] = p4;
        local = fmaf(p4.x, c4.x, local);
        local = fmaf(p4.y, c4.y, local);
        local = fmaf(p4.z, c4.z, local);
        local = fmaf(p4.w, c4.w, local);
    }
    red[threadIdx.x] = local;
    __syncthreads();
    for (int st = 128; st > 0; st >>= 1) {
        if (threadIdx.x < st) red[threadIdx.x] += red[threadIdx.x + st];
        __syncthreads();
    }
    if (threadIdx.x == 0) g_part[row] = red[0];
}

__global__ void kCost(float* __restrict__ cost) {
    PDL_WAIT();
    __shared__ float red[256];
    int b = blockIdx.x;
    float t = 0.0f;
    #pragma unroll
    for (int k = 0; k < 8; k++)
        t += g_part[b * 2048 + threadIdx.x + k * 256];
    red[threadIdx.x] = t;
    __syncthreads();
    for (int st = 128; st > 0; st >>= 1) {
        if (threadIdx.x < st) red[threadIdx.x] += red[threadIdx.x + st];
        __syncthreads();
    }
    if (threadIdx.x == 0) cost[b] = red[0];
}

// Launch with programmatic stream serialization (PDL); on synchronous error,
// fall back to a plain launch so graph capture always records the node.
static inline void pdl_launch(const void* fn, dim3 g, dim3 blk, void** args) {
    cudaLaunchConfig_t cfg = {};
    cfg.gridDim = g;
    cfg.blockDim = blk;
    cfg.dynamicSmemBytes = 0;
    cfg.stream = 0;
    cudaLaunchAttribute at[1];
    at[0].id = cudaLaunchAttributeProgrammaticStreamSerialization;
    at[0].val.programmaticStreamSerializationAllowed = 1;
    cfg.attrs = at;
    cfg.numAttrs = 1;
    if (cudaLaunchKernelExC(&cfg, fn, args) != cudaSuccess) {
        cudaLaunchKernel(fn, g, blk, args, 0, 0);
    }
}

extern "C" void kernel_launch(void* const* d_in, const int* in_sizes, int n_in,
                              void* d_out, int out_size) {
    const float* x = (const float*)d_in[0];
    const float* y = (const float*)d_in[1];
    float* out  = (float*)d_out;
    float* cost = out;                        // 4
    float* pi   = out + 4;                    // 16777216
    float* C    = out + 4 + (size_t)NEL;      // 16777216

    float log_mu = logf(1.0f / 2048.0f + 1e-8f);   // == log_nu (P1==P2)
    float eps_log_mu = 0.1f * log_mu;
    float thresh_tot = 0.1f * (float)BB;           // global-sum form of err<0.1

    kInit<<<(NROWS + 255) / 256, 256>>>();

    {
        void* args[] = { (void*)&x, (void*)&y };
        pdl_launch((const void*)kNorm, dim3(2 * NROWS / 8), dim3(256), args);
    }
    {
        void* args[] = { (void*)&x, (void*)&y, (void*)&C };
        pdl_launch((const void*)kC, dim3(PP / 64, PP / 64, BB), dim3(256), args);
    }
    for (int it = 0; it < 100; it++) {
        {
            void* args[] = { (void*)&C, (void*)&it, (void*)&eps_log_mu };
            pdl_launch((const void*)kU, dim3(NROWS / 8), dim3(512), args);
        }
        {
            void* args[] = { (void*)&C, (void*)&it, (void*)&eps_log_mu,
                             (void*)&thresh_tot };
            pdl_launch((const void*)kV, dim3(BB * (PP / 64)), dim3(1024), args);
        }
    }
    {
        void* args[] = { (void*)&C, (void*)&pi };
        pdl_launch((const void*)kFinal, dim3(NROWS), dim3(256), args);
    }
    {
        void* args[] = { (void*)&cost };
        pdl_launch((const void*)kCost, dim3(BB), dim3(256), args);
    }
}

// round 10
// speedup vs baseline: 1.7470x; 1.1796x over previous
#include <cuda_runtime.h>
#include <math.h>

// Sinkhorn distance, B=4, P=2048, D=64, eps=0.1, max_iter=100, thresh=0.1
// Output layout: [cost(4) | pi(4*2048*2048) | C(4*2048*2048)]
// Iteration kernels are occupancy-tuned single-pass online-LSE sweeps over
// the L2-resident C; PDL hides launch gaps.

#define BB 4
#define PP 2048
#define DD 64
#define NROWS (BB*PP)                 // 8192
#define NEL ((size_t)BB*PP*PP)        // 16777216
#define S_CONST 14.426950408889634f   // (1/eps) * log2(e), eps = 0.1
#define EPSLN2  0.069314718055994531f // eps * ln2

__device__ float g_u[NROWS];
__device__ float g_v[NROWS];
__device__ float g_err[NROWS];
__device__ float g_xn[NROWS];
__device__ float g_yn[NROWS];
__device__ float g_part[NROWS];
__device__ int   g_done[104];

#define PDL_WAIT() asm volatile("griddepcontrol.wait;" ::: "memory")

__device__ __forceinline__ float ex2(float x) {
    float r;
    asm("ex2.approx.ftz.f32 %0, %1;" : "=f"(r) : "f"(x));
    return r;
}

// Exact online LSE step (log2 domain): keeps true running max.
__device__ __forceinline__ void olse(float& m, float& s, float a) {
    float e = ex2(0.0f - fabsf(m - a));
    s = (a > m) ? fmaf(s, e, 1.0f) : (s + e);
    m = fmaxf(m, a);
}

// Merge two (max,sum) log2-domain accumulators.
__device__ __forceinline__ void lse_merge(float& m, float& s, float m2, float s2) {
    float M = fmaxf(m, m2);
    s = fmaf(s, ex2(m - M), s2 * ex2(m2 - M));
    m = M;
}

__global__ void kInit() {
    int t = blockIdx.x * 256 + threadIdx.x;
    if (t < NROWS) { g_u[t] = 0.0f; g_v[t] = 0.0f; }
    if (t == 0) g_done[0] = 0;
}

// Row norms. One warp per row.
__global__ void kNorm(const float* __restrict__ x, const float* __restrict__ y) {
    PDL_WAIT();
    int lane = threadIdx.x & 31;
    int gw = blockIdx.x * 8 + (threadIdx.x >> 5);
    const float* src = (gw < NROWS) ? x : y;
    float* dst = (gw < NROWS) ? g_xn : g_yn;
    int row = gw & (NROWS - 1);
    float2 v = ((const float2*)src)[row * 32 + lane];
    float s = fmaf(v.x, v.x, v.y * v.y);
    #pragma unroll
    for (int off = 16; off > 0; off >>= 1)
        s += __shfl_xor_sync(0xffffffffu, s, off);
    if (lane == 0) dst[row] = s;
}

// C[b,i,j] = ||x_i||^2 + ||y_j||^2 - 2 x_i . y_j
__global__ __launch_bounds__(256) void kC(const float* __restrict__ x,
                                          const float* __restrict__ y,
                                          float* __restrict__ Cout) {
    PDL_WAIT();
    __shared__ float xs[64][68];
    __shared__ float ys[64][68];
    int b  = blockIdx.z;
    int i0 = blockIdx.y * 64;
    int j0 = blockIdx.x * 64;
    for (int idx = threadIdx.x; idx < 64 * 64; idx += 256) {
        int i = idx >> 6, d = idx & 63;
        xs[d][i] = x[((size_t)(b * PP + i0 + i)) * DD + d];
        ys[d][i] = y[((size_t)(b * PP + j0 + i)) * DD + d];
    }
    __syncthreads();
    int tx = threadIdx.x & 15, ty = threadIdx.x >> 4;
    float acc[4][4] = {};
    #pragma unroll 16
    for (int d = 0; d < 64; d++) {
        float4 xv = *(const float4*)&xs[d][ty * 4];
        float4 yv = *(const float4*)&ys[d][tx * 4];
        acc[0][0] = fmaf(xv.x, yv.x, acc[0][0]);
        acc[0][1] = fmaf(xv.x, yv.y, acc[0][1]);
        acc[0][2] = fmaf(xv.x, yv.z, acc[0][2]);
        acc[0][3] = fmaf(xv.x, yv.w, acc[0][3]);
        acc[1][0] = fmaf(xv.y, yv.x, acc[1][0]);
        acc[1][1] = fmaf(xv.y, yv.y, acc[1][1]);
        acc[1][2] = fmaf(xv.y, yv.z, acc[1][2]);
        acc[1][3] = fmaf(xv.y, yv.w, acc[1][3]);
        acc[2][0] = fmaf(xv.z, yv.x, acc[2][0]);
        acc[2][1] = fmaf(xv.z, yv.y, acc[2][1]);
        acc[2][2] = fmaf(xv.z, yv.z, acc[2][2]);
        acc[2][3] = fmaf(xv.z, yv.w, acc[2][3]);
        acc[3][0] = fmaf(xv.w, yv.x, acc[3][0]);
        acc[3][1] = fmaf(xv.w, yv.y, acc[3][1]);
        acc[3][2] = fmaf(xv.w, yv.z, acc[3][2]);
        acc[3][3] = fmaf(xv.w, yv.w, acc[3][3]);
    }
    int gi = b * PP + i0 + ty * 4;
    int gj = b * PP + j0 + tx * 4;
    float xn[4] = {g_xn[gi], g_xn[gi + 1], g_xn[gi + 2], g_xn[gi + 3]};
    float yn[4] = {g_yn[gj], g_yn[gj + 1], g_yn[gj + 2], g_yn[gj + 3]};
    #pragma unroll
    for (int r = 0; r < 4; r++) {
        float4 o;
        o.x = fmaf(-2.0f, acc[r][0], xn[r] + yn[0]);
        o.y = fmaf(-2.0f, acc[r][1], xn[r] + yn[1]);
        o.z = fmaf(-2.0f, acc[r][2], xn[r] + yn[2]);
        o.w = fmaf(-2.0f, acc[r][3], xn[r] + yn[3]);
        ((float4*)(Cout + ((size_t)(b * PP + i0 + ty * 4 + r)) * PP + j0))[tx] = o;
    }
}

// u update: per-row LSE_j((v_j - C_ij)/eps). 8 rows/block, 64 threads/row,
// single-pass online LSE (no register cache -> high occupancy).
__global__ __launch_bounds__(512, 3) void kU(const float* __restrict__ C,
                                             int iter, float eps_log_mu) {
    PDL_WAIT();
    if (g_done[iter]) return;
    __shared__ __align__(16) float vs[PP];
    __shared__ float wm[16];
    __shared__ float ws[16];
    int tid = threadIdx.x;
    int b = blockIdx.x >> 8;                 // 256 blocks per batch
    const float4* vb = (const float4*)(g_v + b * PP);
    for (int t = tid; t < PP / 4; t += 512) {
        float4 v = vb[t];
        v.x *= S_CONST; v.y *= S_CONST; v.z *= S_CONST; v.w *= S_CONST;
        ((float4*)vs)[t] = v;
    }
    __syncthreads();
    int w    = tid >> 5;
    int lane = tid & 31;
    int r    = tid >> 6;                     // row-in-block 0..7
    int t64  = tid & 63;
    int row  = blockIdx.x * 8 + r;
    const float4* Crow = (const float4*)(C + (size_t)row * PP);
    const float4* vs4  = (const float4*)vs;

    float m0 = -INFINITY, m1 = -INFINITY, m2 = -INFINITY, m3 = -INFINITY;
    float s0 = 0.0f, s1 = 0.0f, s2 = 0.0f, s3 = 0.0f;
    #pragma unroll
    for (int k = 0; k < 8; k++) {
        int idx = t64 + k * 64;
        float4 c4 = __ldcg(Crow + idx);
        float4 v4 = vs4[idx];
        olse(m0, s0, fmaf(c4.x, -S_CONST, v4.x));
        olse(m1, s1, fmaf(c4.y, -S_CONST, v4.y));
        olse(m2, s2, fmaf(c4.z, -S_CONST, v4.z));
        olse(m3, s3, fmaf(c4.w, -S_CONST, v4.w));
    }
    lse_merge(m0, s0, m1, s1);
    lse_merge(m2, s2, m3, s3);
    lse_merge(m0, s0, m2, s2);
    #pragma unroll
    for (int off = 16; off > 0; off >>= 1) {
        float mo = __shfl_xor_sync(0xffffffffu, m0, off);
        float so = __shfl_xor_sync(0xffffffffu, s0, off);
        lse_merge(m0, s0, mo, so);
    }
    if (lane == 0) { wm[w] = m0; ws[w] = s0; }
    __syncthreads();
    if (t64 == 0) {
        float M = wm[2 * r], S = ws[2 * r];
        lse_merge(M, S, wm[2 * r + 1], ws[2 * r + 1]);
        float lse2 = M + __log2f(S);
        float un = fmaf(-EPSLN2, lse2, eps_log_mu);
        float old = g_u[row];
        g_u[row] = un;
        g_err[row] = fabsf(un - old);
    }
}

// v update: per-col LSE, single pass. 256 blocks x 512 threads.
// Block = 32-col stripe x 2048 rows; warp w owns row group w*128, 2 chains.
__global__ __launch_bounds__(512, 3) void kV(const float* __restrict__ C,
                                             int iter, float eps_log_nu,
                                             float thresh_tot) {
    PDL_WAIT();
    __shared__ __align__(16) float us[PP];
    __shared__ float pm[16][32];
    __shared__ float ps[16][32];
    __shared__ float red[512];
    int done = g_done[iter];
    int tid = threadIdx.x;
    int b  = blockIdx.x >> 6;                // 64 stripes per batch
    int j0 = (blockIdx.x & 63) * 32;
    int w = tid >> 5, lane = tid & 31;

    if (!done) {
        const float4* ub = (const float4*)(g_u + b * PP);
        for (int t = tid; t < PP / 4; t += 512) {
            float4 u4 = ub[t];
            u4.x *= S_CONST; u4.y *= S_CONST; u4.z *= S_CONST; u4.w *= S_CONST;
            ((float4*)us)[t] = u4;
        }
        __syncthreads();
        int j  = j0 + lane;
        int r0 = w * 128;
        const float* pA = C + (size_t)b * PP * PP + (size_t)r0 * PP + j;
        const float* pB = pA + (size_t)64 * PP;
        const float* uA = us + r0;
        float mA = -INFINITY, sA = 0.0f, mB = -INFINITY, sB = 0.0f;
        #pragma unroll 8
        for (int rr = 0; rr < 64; rr++) {
            float cA = __ldcg(pA); pA += PP;
            float cB = __ldcg(pB); pB += PP;
            olse(mA, sA, fmaf(cA, -S_CONST, uA[rr]));
            olse(mB, sB, fmaf(cB, -S_CONST, uA[rr + 64]));
        }
        lse_merge(mA, sA, mB, sB);
        pm[w][lane] = mA;
        ps[w][lane] = sA;
        __syncthreads();
        if (tid < 32) {
            float M = pm[0][tid], S = ps[0][tid];
            #pragma unroll
            for (int k = 1; k < 16; k++)
                lse_merge(M, S, pm[k][tid], ps[k][tid]);
            float lse2 = M + __log2f(S);
            g_v[b * PP + j0 + tid] = fmaf(-EPSLN2, lse2, eps_log_nu);
        }
    }

    // done flag (block 0, deterministic fixed-order reduction of g_err)
    if (blockIdx.x == 0) {
        if (done) {
            if (tid == 0) g_done[iter + 1] = 1;
            return;
        }
        __syncthreads();
        float ts = 0.0f;
        #pragma unroll
        for (int k = 0; k < NROWS / 512; k++)
            ts += g_err[tid + k * 512];
        red[tid] = ts;
        __syncthreads();
        for (int st = 256; st > 0; st >>= 1) {
            if (tid < st) red[tid] += red[tid + st];
            __syncthreads();
        }
        if (tid == 0) g_done[iter + 1] = (red[0] < thresh_tot) ? 1 : 0;
    }
}

// pi = exp2((u+v-C)*S); per-row partial of sum(pi*C)
__global__ __launch_bounds__(256) void kFinal(const float* __restrict__ C,
                                              float* __restrict__ pi) {
    PDL_WAIT();
    __shared__ __align__(16) float wsm[PP];
    __shared__ float red[256];
    int row = blockIdx.x;
    int b = row >> 11;
    float ui = g_u[row];
    const float4* vb = (const float4*)(g_v + b * PP);
    for (int t = threadIdx.x; t < PP / 4; t += 256) {
        float4 v4 = vb[t];
        v4.x = (ui + v4.x) * S_CONST;
        v4.y = (ui + v4.y) * S_CONST;
        v4.z = (ui + v4.z) * S_CONST;
        v4.w = (ui + v4.w) * S_CONST;
        ((float4*)wsm)[t] = v4;
    }
    __syncthreads();
    const float4* Crow = (const float4*)(C + (size_t)row * PP);
    float4* prow = (float4*)(pi + (size_t)row * PP);
    const float4* ws4 = (const float4*)wsm;
    float local = 0.0f;
    #pragma unroll
    for (int k = 0; k < 2; k++) {
        int idx = threadIdx.x + k * 256;
        float4 c4 = Crow[idx];
        float4 w4 = ws4[idx];
        float4 p4;
        p4.x = ex2(fmaf(c4.x, -S_CONST, w4.x));
        p4.y = ex2(fmaf(c4.y, -S_CONST, w4.y));
        p4.z = ex2(fmaf(c4.z, -S_CONST, w4.z));
        p4.w = ex2(fmaf(c4.w, -S_CONST, w4.w));
        prow[idx] = p4;
        local = fmaf(p4.x, c4.x, local);
        local = fmaf(p4.y, c4.y, local);
        local = fmaf(p4.z, c4.z, local);
        local = fmaf(p4.w, c4.w, local);
    }
    red[threadIdx.x] = local;
    __syncthreads();
    for (int st = 128; st > 0; st >>= 1) {
        if (threadIdx.x < st) red[threadIdx.x] += red[threadIdx.x + st];
        __syncthreads();
    }
    if (threadIdx.x == 0) g_part[row] = red[0];
}

__global__ void kCost(float* __restrict__ cost) {
    PDL_WAIT();
    __shared__ float red[256];
    int b = blockIdx.x;
    float t = 0.0f;
    #pragma unroll
    for (int k = 0; k < 8; k++)
        t += g_part[b * 2048 + threadIdx.x + k * 256];
    red[threadIdx.x] = t;
    __syncthreads();
    for (int st = 128; st > 0; st >>= 1) {
        if (threadIdx.x < st) red[threadIdx.x] += red[threadIdx.x + st];
        __syncthreads();
    }
    if (threadIdx.x == 0) cost[b] = red[0];
}

// Launch with programmatic stream serialization (PDL); fall back to plain.
static inline void pdl_launch(const void* fn, dim3 g, dim3 blk, void** args) {
    cudaLaunchConfig_t cfg = {};
    cfg.gridDim = g;
    cfg.blockDim = blk;
    cfg.dynamicSmemBytes = 0;
    cfg.stream = 0;
    cudaLaunchAttribute at[1];
    at[0].id = cudaLaunchAttributeProgrammaticStreamSerialization;
    at[0].val.programmaticStreamSerializationAllowed = 1;
    cfg.attrs = at;
    cfg.numAttrs = 1;
    if (cudaLaunchKernelExC(&cfg, fn, args) != cudaSuccess) {
        cudaLaunchKernel(fn, g, blk, args, 0, 0);
    }
}

extern "C" void kernel_launch(void* const* d_in, const int* in_sizes, int n_in,
                              void* d_out, int out_size) {
    const float* x = (const float*)d_in[0];
    const float* y = (const float*)d_in[1];
    float* out  = (float*)d_out;
    float* cost = out;                        // 4
    float* pi   = out + 4;                    // 16777216
    float* C    = out + 4 + (size_t)NEL;      // 16777216

    float log_mu = logf(1.0f / 2048.0f + 1e-8f);   // == log_nu (P1==P2)
    float eps_log_mu = 0.1f * log_mu;
    float thresh_tot = 0.1f * (float)BB;           // global-sum form of err<0.1

    kInit<<<(NROWS + 255) / 256, 256>>>();

    {
        void* args[] = { (void*)&x, (void*)&y };
        pdl_launch((const void*)kNorm, dim3(2 * NROWS / 8), dim3(256), args);
    }
    {
        void* args[] = { (void*)&x, (void*)&y, (void*)&C };
        pdl_launch((const void*)kC, dim3(PP / 64, PP / 64, BB), dim3(256), args);
    }
    for (int it = 0; it < 100; it++) {
        {
            void* args[] = { (void*)&C, (void*)&it, (void*)&eps_log_mu };
            pdl_launch((const void*)kU, dim3(NROWS / 8), dim3(512), args);
        }
        {
            void* args[] = { (void*)&C, (void*)&it, (void*)&eps_log_mu,
                             (void*)&thresh_tot };
            pdl_launch((const void*)kV, dim3(BB * (PP / 32)), dim3(512), args);
        }
    }
    {
        void* args[] = { (void*)&C, (void*)&pi };
        pdl_launch((const void*)kFinal, dim3(NROWS), dim3(256), args);
    }
    {
        void* args[] = { (void*)&cost };
        pdl_launch((const void*)kCost, dim3(BB), dim3(256), args);
    }
}